// round 8
// baseline (speedup 1.0000x reference)
#include <cuda_runtime.h>
#include <cstdint>
#include <cfloat>

#define NH    218
#define NHP   224        // padded h stride (16B-aligned rows)
#define NSUB  47524      // 218*218
#define NROWS 64         // B * C_OUT * C_IN
#define OG    28         // octo-groups per h1 row (28*8 = 224 >= 218)
#define TPB   224        // 8 h1 rows * 28 octo-groups

typedef unsigned long long ull;

// ---------------- device globals (no allocations allowed) ----------------
__device__ __align__(16) float g_Wn[32 * 24 * 16];          // -2*Kstruct, [oi][p][c]
__device__ float g_c2[32];                                   // ||K||^2+||R||^2+||C||^2
__device__ __align__(16) float g_rpn[2 * 32 * 24 * NHP];     // rpart [b][oi][p][h1]
__device__ __align__(16) float g_cpn[2 * 32 * 24 * NHP];     // cpart [b][oi][p][h2]
__device__ float g_pmax[NROWS][NH];
__device__ float g_psum[NROWS][NH];
__device__ float g_fac[NROWS][NH];
__device__ __align__(16) float g_sims[(size_t)NROWS * NSUB]; // m, then exp(m - blkmax)

__constant__ unsigned char c_P[24][4] = {
  {0,1,2,3},{0,1,3,2},{0,2,1,3},{0,2,3,1},{0,3,1,2},{0,3,2,1},
  {1,0,2,3},{1,0,3,2},{1,2,0,3},{1,2,3,0},{1,3,0,2},{1,3,2,0},
  {2,0,1,3},{2,0,3,1},{2,1,0,3},{2,1,3,0},{2,3,0,1},{2,3,1,0},
  {3,0,1,2},{3,0,2,1},{3,1,0,2},{3,1,2,0},{3,2,0,1},{3,2,1,0}
};

// ---------------- packed f32x2 helpers -----------------------------------
__device__ __forceinline__ ull dup2(float f) {
    ull r;
    asm("mov.b64 %0, {%1, %1};" : "=l"(r) : "f"(f));
    return r;
}
__device__ __forceinline__ ull pk2(float a, float b) {
    ull r;
    asm("mov.b64 %0, {%1, %2};" : "=l"(r) : "f"(a), "f"(b));
    return r;
}
__device__ __forceinline__ ull add2(ull a, ull b) {
    ull r;
    asm("add.rn.f32x2 %0, %1, %2;" : "=l"(r) : "l"(a), "l"(b));
    return r;
}
#define FMA2(acc, x, w) asm("fma.rn.f32x2 %0, %1, %2, %0;" : "+l"(acc) : "l"(x), "l"(w))
#define UNPK(v, lo, hi) asm("mov.b64 {%0, %1}, %2;" : "=f"(lo), "=f"(hi) : "l"(v))

// ---------------- prep 1: weights + c2 ------------------------------------
__global__ void prep_w_kernel(const float* __restrict__ ks,
                              const float* __restrict__ kr,
                              const float* __restrict__ kc) {
    int tid = threadIdx.x;
    if (tid < 32) {
        int oi = tid; float s = 0.0f;
        const float* a = ks + oi * 16;
        #pragma unroll
        for (int j = 0; j < 16; j++) s += a[j] * a[j];
        const float* r = kr + oi * 4; const float* c = kc + oi * 4;
        #pragma unroll
        for (int j = 0; j < 4; j++) { s += r[j] * r[j]; s += c[j] * c[j]; }
        g_c2[oi] = s;
    }
    for (int e = tid; e < 32 * 24 * 16; e += blockDim.x) {
        int c = e & 15; int t2 = e >> 4;
        int p = t2 % 24; int oi = t2 / 24;
        int a = c >> 2, bb = c & 3;
        float val = ks[oi * 16 + (int)c_P[p][a] * 4 + (int)c_P[p][bb]];
        g_Wn[(oi * 24 + p) * 16 + c] = -2.0f * val;
    }
}

// ---------------- prep 2: rp/cp tables (scalar-perm, padded h) ------------
__global__ void prep_tab_kernel(const float* __restrict__ types,
                                const float* __restrict__ kr,
                                const float* __restrict__ kc) {
    int idx = blockIdx.x, tid = threadIdx.x;
    int b = idx / NH, h = idx - b * NH;
    for (int e = tid; e < 768; e += blockDim.x) {
        int oi = e / 24, p = e % 24;
        int i = oi & 3;
        const float* tp = types + (b * 4 + i) * 224 + h;
        float t0 = tp[0], t1 = tp[2], t2 = tp[4], t3 = tp[6];
        float t2s = t0 * t0 + t1 * t1 + t2 * t2 + t3 * t3;
        const float* krp = kr + oi * 4;
        const float* kcp = kc + oi * 4;
        float rd = t0 * krp[c_P[p][0]] + t1 * krp[c_P[p][1]] + t2 * krp[c_P[p][2]] + t3 * krp[c_P[p][3]];
        float cd = t0 * kcp[c_P[p][0]] + t1 * kcp[c_P[p][1]] + t2 * kcp[c_P[p][2]] + t3 * kcp[c_P[p][3]];
        size_t lin = ((size_t)(b * 32 + oi) * 24 + p) * NHP + h;
        g_rpn[lin] = t2s - 2.0f * rd;
        g_cpn[lin] = t2s - 2.0f * cd;
    }
}

// ---------------- prep 3: h_mean closed form -------------------------------
__global__ void prep_h_kernel(const float* __restrict__ feats, float* __restrict__ out) {
    int b = blockIdx.x, f = threadIdx.x;
    float acc = 0.0f;
    for (int n = 0; n < 224; n++) {
        int lo = (n >= NH) ? ((n - (NH - 2)) >> 1) : 0;
        int hi = min(3, n >> 1);
        acc += (float)(hi - lo + 1) * feats[(b * 224 + n) * 128 + f];
    }
    out[b * 128 + f] = acc * (2.0f / (float)NH);
}

// ---------------- sims: 8 subwindows per thread ----------------------------
// thread = (lh in 0..7, octo-group u in 0..27): subs h2 = 8u..8u+7
// Overlap: 8 subs need graph cols h2b..h2b+13 per row a = 7 packed f32x2.
// Per (p, c): ONE LDS.32 weight -> 4 FMA2 (4 sub-pair accumulators).
// block = 224; grid = (28 h1-tiles, B=2, 4 o-pairs).
__global__ void __launch_bounds__(TPB, 2)
sims_kernel(const float* __restrict__ graph) {
    __shared__ __align__(16) float sw[8 * 24 * 16];   // 12 KB: [oiL][p][c]
    __shared__ float    srp[8][8][24];                // rpart for 8 h1 (6 KB)
    __shared__ float    sc2s[8];
    __shared__ unsigned smaxu[8][8];
    __shared__ float    smaxf[8][8];
    __shared__ float    ssumv[8][8];

    int t  = threadIdx.x;
    int b  = blockIdx.y;
    int zo = blockIdx.z;              // o-pair index: o = zo*2 + oL
    int h1base = blockIdx.x * 8;

    {
        const float4* srcw = (const float4*)(g_Wn + zo * 8 * 384);
        float4* dstw = (float4*)sw;
        for (int e = t; e < 768; e += TPB) dstw[e] = srcw[e];
        for (int e = t; e < 1536; e += TPB) {
            int lh = e / 192, r = e % 192, oiL = r / 24, p = r % 24;
            int h1s = min(h1base + lh, NH - 1);
            srp[lh][oiL][p] = g_rpn[((size_t)(b * 32 + zo * 8 + oiL) * 24 + p) * NHP + h1s];
        }
        if (t < 8) sc2s[t] = g_c2[zo * 8 + t];
        if (t < 64) { smaxu[t >> 3][t & 7] = 0u; ssumv[t >> 3][t & 7] = 0.0f; }
    }
    __syncthreads();

    int lh = t / OG, u = t - lh * OG;
    int h1 = h1base + lh;
    bool h1v = h1 < NH;
    int h1c = h1v ? h1 : NH - 1;
    int h2b = 8 * u;
    int nk = h1v ? ((h2b + 8 <= NH) ? 8 : NH - h2b) : 0;  // 8, 2 (u=27), or 0
    bool fullq = (u < OG - 1);

    #pragma unroll 1
    for (int i = 0; i < 4; i++) {
        ull xq[4][7];
        float x2[8];
        #pragma unroll
        for (int s = 0; s < 8; s++) x2[s] = 0.0f;
        const float* gp = graph + (((size_t)(b * 4 + i) * 224) + h1c) * 224 + h2b;
        #pragma unroll
        for (int a = 0; a < 4; a++) {
            const float* ad = gp + (2 * a) * 224;
            float4 v0 = *(const float4*)ad;          // g0..g3
            float4 v1 = *(const float4*)(ad + 4);    // g4..g7
            float4 v2 = fullq ? *(const float4*)(ad + 8)
                              : make_float4(0.f, 0.f, 0.f, 0.f);   // g8..g11
            float2 v3 = fullq ? *(const float2*)(ad + 12)
                              : make_float2(0.f, 0.f);             // g12..g13
            float g[14] = {v0.x, v0.y, v0.z, v0.w, v1.x, v1.y, v1.z, v1.w,
                           v2.x, v2.y, v2.z, v2.w, v3.x, v3.y};
            #pragma unroll
            for (int j = 0; j < 7; j++) xq[a][j] = pk2(g[2 * j], g[2 * j + 1]);
            #pragma unroll
            for (int s = 0; s < 8; s++) {
                x2[s] = fmaf(g[s], g[s],
                        fmaf(g[s + 2], g[s + 2],
                        fmaf(g[s + 4], g[s + 4],
                        fmaf(g[s + 6], g[s + 6], x2[s]))));
            }
        }
        ull b2[4];
        #pragma unroll
        for (int tt = 0; tt < 4; tt++) b2[tt] = pk2(x2[2 * tt], x2[2 * tt + 1]);

        #pragma unroll 1
        for (int oL = 0; oL < 2; oL++) {
            int oiL = oL * 4 + i;
            const float* wp  = sw + oiL * 384;
            const float* rpp = &srp[lh][oiL][0];
            const float* cpg = g_cpn + ((size_t)(b * 32 + zo * 8 + oiL) * 24) * NHP + h2b;
            float sc2v = sc2s[oiL];
            float m[8];
            #pragma unroll
            for (int s = 0; s < 8; s++) m[s] = FLT_MAX;
            #pragma unroll 4
            for (int p = 0; p < 24; p++) {
                const float* cpp = cpg + p * NHP;
                ulonglong2 cpa = *(const ulonglong2*)cpp;        // h2b..+3
                ulonglong2 cpb = *(const ulonglong2*)(cpp + 4);  // +4..+7
                ull crp2 = dup2(sc2v + rpp[p]);
                ull a0 = add2(add2(b2[0], crp2), cpa.x);
                ull a1 = add2(add2(b2[1], crp2), cpa.y);
                ull a2 = add2(add2(b2[2], crp2), cpb.x);
                ull a3 = add2(add2(b2[3], crp2), cpb.y);
                const float* wq = wp + p * 16;
                #pragma unroll
                for (int a = 0; a < 4; a++) {
                    #pragma unroll
                    for (int bb = 0; bb < 4; bb++) {
                        ull w2 = dup2(wq[a * 4 + bb]);
                        FMA2(a0, xq[a][bb],     w2);
                        FMA2(a1, xq[a][bb + 1], w2);
                        FMA2(a2, xq[a][bb + 2], w2);
                        FMA2(a3, xq[a][bb + 3], w2);
                    }
                }
                float d0, d1, d2, d3, d4, d5, d6, d7;
                UNPK(a0, d0, d1); UNPK(a1, d2, d3);
                UNPK(a2, d4, d5); UNPK(a3, d6, d7);
                m[0] = fminf(m[0], d0); m[1] = fminf(m[1], d1);
                m[2] = fminf(m[2], d2); m[3] = fminf(m[3], d3);
                m[4] = fminf(m[4], d4); m[5] = fminf(m[5], d5);
                m[6] = fminf(m[6], d6); m[7] = fminf(m[7], d7);
            }
            if (nk) {
                int row = b * 32 + zo * 8 + oiL;
                float* sp = g_sims + (size_t)row * NSUB + h1 * NH + h2b;
                float tm;
                if (nk == 8) {
                    *(float2*)(sp + 0) = make_float2(m[0], m[1]);
                    *(float2*)(sp + 2) = make_float2(m[2], m[3]);
                    *(float2*)(sp + 4) = make_float2(m[4], m[5]);
                    *(float2*)(sp + 6) = make_float2(m[6], m[7]);
                    tm = fmaxf(fmaxf(fmaxf(m[0], m[1]), fmaxf(m[2], m[3])),
                               fmaxf(fmaxf(m[4], m[5]), fmaxf(m[6], m[7])));
                } else {   // nk == 2
                    *(float2*)sp = make_float2(m[0], m[1]);
                    tm = fmaxf(m[0], m[1]);
                }
                unsigned uu  = __float_as_uint(tm);
                unsigned key = (uu & 0x80000000u) ? ~uu : (uu | 0x80000000u);
                atomicMax(&smaxu[lh][oiL], key);
            }
        }
    }

    __syncthreads();
    if (t < 64) {
        unsigned uu = smaxu[t >> 3][t & 7];
        smaxf[t >> 3][t & 7] = (uu & 0x80000000u) ? __uint_as_float(uu & 0x7fffffffu)
                                                  : __uint_as_float(~uu);
    }
    __syncthreads();

    // phase 2: in-place exp (thread re-reads only its own writes)
    if (nk) {
        #pragma unroll 1
        for (int oiL = 0; oiL < 8; oiL++) {
            int row = b * 32 + zo * 8 + oiL;
            float mx = smaxf[lh][oiL];
            float* sp = g_sims + (size_t)row * NSUB + h1 * NH + h2b;
            float ssv = 0.0f;
            if (nk == 8) {
                #pragma unroll
                for (int j = 0; j < 4; j++) {
                    float2 v = *(float2*)(sp + 2 * j);
                    float e0 = __expf(v.x - mx), e1 = __expf(v.y - mx);
                    *(float2*)(sp + 2 * j) = make_float2(e0, e1);
                    ssv += e0 + e1;
                }
            } else {
                float2 v = *(float2*)sp;
                float e0 = __expf(v.x - mx), e1 = __expf(v.y - mx);
                *(float2*)sp = make_float2(e0, e1);
                ssv = e0 + e1;
            }
            atomicAdd(&ssumv[lh][oiL], ssv);
        }
    }
    __syncthreads();
    if (t < 64) {
        int lh2 = t >> 3, oiL = t & 7, h1w = h1base + lh2;
        if (h1w < NH) {
            int row = b * 32 + zo * 8 + oiL;
            g_pmax[row][h1w] = smaxf[lh2][oiL];
            g_psum[row][h1w] = ssumv[lh2][oiL];
        }
    }
}

// ---------------- combine: global max/sum + factor table -------------------
__global__ void combine_kernel() {
    __shared__ float red[256];
    int row = blockIdx.x, tid = threadIdx.x;
    float pm = (tid < NH) ? g_pmax[row][tid] : -FLT_MAX;
    red[tid] = pm; __syncthreads();
    #pragma unroll
    for (int st = 128; st; st >>= 1) {
        if (tid < st) red[tid] = fmaxf(red[tid], red[tid + st]);
        __syncthreads();
    }
    float gmx = red[0];
    __syncthreads();
    float ex = (tid < NH) ? __expf(pm - gmx) : 0.0f;
    red[tid] = (tid < NH) ? g_psum[row][tid] * ex : 0.0f;
    __syncthreads();
    #pragma unroll
    for (int st = 128; st; st >>= 1) {
        if (tid < st) red[tid] += red[tid + st];
        __syncthreads();
    }
    float S = red[0];
    if (tid < NH) g_fac[row][tid] = ex / S;
}

// ---------------- writeout: grid-stride float4 streaming -------------------
__global__ void writeout_kernel(float* __restrict__ out) {
    int row = blockIdx.y;
    const float* fr = g_fac[row];
    const float* sp = g_sims + (size_t)row * NSUB;
    float* op = out + 256 + (size_t)row * NSUB;
    int idx = (blockIdx.x * 1024 + threadIdx.x) * 4;
    if (idx + 4 <= NSUB) {
        float4 e = *(const float4*)(sp + idx);
        int h1a = idx / NH, h1b = (idx + 1) / NH, h1c2 = (idx + 2) / NH, h1d = (idx + 3) / NH;
        float4 r;
        r.x = (1.0f - e.x * fr[h1a]) * (1.0f / (float)NSUB);
        r.y = (1.0f - e.y * fr[h1b]) * (1.0f / (float)NSUB);
        r.z = (1.0f - e.z * fr[h1c2]) * (1.0f / (float)NSUB);
        r.w = (1.0f - e.w * fr[h1d]) * (1.0f / (float)NSUB);
        *(float4*)(op + idx) = r;
    } else {
        for (int j = idx; j < NSUB; j++)
            op[j] = (1.0f - sp[j] * fr[j / NH]) * (1.0f / (float)NSUB);
    }
}

// ---------------- launch ---------------------------------------------------
extern "C" void kernel_launch(void* const* d_in, const int* in_sizes, int n_in,
                              void* d_out, int out_size) {
    const float* graph    = (const float*)d_in[0];
    const float* types    = (const float*)d_in[1];
    const float* features = (const float*)d_in[2];
    const float* ks       = (const float*)d_in[3];
    const float* kr       = (const float*)d_in[4];
    const float* kc       = (const float*)d_in[5];
    float* out = (float*)d_out;

    prep_w_kernel<<<1, 256>>>(ks, kr, kc);
    prep_tab_kernel<<<2 * NH, 256>>>(types, kr, kc);
    prep_h_kernel<<<2, 128>>>(features, out);
    sims_kernel<<<dim3(OG, 2, 4), TPB>>>(graph);      // launch #4 -> ncu capture
    combine_kernel<<<NROWS, 256>>>();
    writeout_kernel<<<dim3((NSUB + 4095) / 4096, NROWS), 1024>>>(out);
}

// round 10
// speedup vs baseline: 1.0902x; 1.0902x over previous
#include <cuda_runtime.h>
#include <cstdint>
#include <cfloat>

#define NH    218
#define NHP   224        // padded h stride (16B-aligned rows)
#define NSUB  47524      // 218*218
#define NROWS 64         // B * C_OUT * C_IN
#define QG    55         // quad-groups per h1 row (55*4 = 220 >= 218)
#define TPB   220        // 4 h1 rows * 55 quad-groups

typedef unsigned long long ull;

// ---------------- device globals (no allocations allowed) ----------------
__device__ __align__(16) float g_Wn[32 * 24 * 16];          // -2*Kstruct, [oi][p][c]
__device__ float g_c2[32];                                   // ||K||^2+||R||^2+||C||^2
__device__ __align__(16) float g_rpn[2 * 32 * 24 * NHP];     // rpart [b][oi][p][h1]
__device__ __align__(16) float g_cpn[2 * 32 * 24 * NHP];     // cpart [b][oi][p][h2]
__device__ float g_pmax[NROWS][NH];
__device__ float g_psum[NROWS][NH];
__device__ float g_fac[NROWS][NH];
__device__ __align__(16) float g_sims[(size_t)NROWS * NSUB]; // m, then exp(m - blkmax)

__constant__ unsigned char c_P[24][4] = {
  {0,1,2,3},{0,1,3,2},{0,2,1,3},{0,2,3,1},{0,3,1,2},{0,3,2,1},
  {1,0,2,3},{1,0,3,2},{1,2,0,3},{1,2,3,0},{1,3,0,2},{1,3,2,0},
  {2,0,1,3},{2,0,3,1},{2,1,0,3},{2,1,3,0},{2,3,0,1},{2,3,1,0},
  {3,0,1,2},{3,0,2,1},{3,1,0,2},{3,1,2,0},{3,2,0,1},{3,2,1,0}
};

// ---------------- packed f32x2 helpers -----------------------------------
__device__ __forceinline__ ull dup2(float f) {
    ull r;
    asm("mov.b64 %0, {%1, %1};" : "=l"(r) : "f"(f));
    return r;
}
__device__ __forceinline__ ull pk2(float a, float b) {
    ull r;
    asm("mov.b64 %0, {%1, %2};" : "=l"(r) : "f"(a), "f"(b));
    return r;
}
__device__ __forceinline__ ull add2(ull a, ull b) {
    ull r;
    asm("add.rn.f32x2 %0, %1, %2;" : "=l"(r) : "l"(a), "l"(b));
    return r;
}
#define FMA2(acc, x, w) asm("fma.rn.f32x2 %0, %1, %2, %0;" : "+l"(acc) : "l"(x), "l"(w))
#define UNPK(v, lo, hi) asm("mov.b64 {%0, %1}, %2;" : "=f"(lo), "=f"(hi) : "l"(v))

// ---------------- fused prep: weights+c2 / h_mean / rp-cp tables ----------
__global__ void prep_all_kernel(const float* __restrict__ types,
                                const float* __restrict__ feats,
                                const float* __restrict__ ks,
                                const float* __restrict__ kr,
                                const float* __restrict__ kc,
                                float* __restrict__ out) {
    int bid = blockIdx.x, tid = threadIdx.x;
    if (bid == 0) {
        if (tid < 32) {
            int oi = tid; float s = 0.0f;
            const float* a = ks + oi * 16;
            #pragma unroll
            for (int j = 0; j < 16; j++) s += a[j] * a[j];
            const float* r = kr + oi * 4; const float* c = kc + oi * 4;
            #pragma unroll
            for (int j = 0; j < 4; j++) { s += r[j] * r[j]; s += c[j] * c[j]; }
            g_c2[oi] = s;
        }
        for (int e = tid; e < 32 * 24 * 16; e += blockDim.x) {
            int c = e & 15; int t2 = e >> 4;
            int p = t2 % 24; int oi = t2 / 24;
            int a = c >> 2, bb = c & 3;
            float val = ks[oi * 16 + (int)c_P[p][a] * 4 + (int)c_P[p][bb]];
            g_Wn[(oi * 24 + p) * 16 + c] = -2.0f * val;
        }
    } else if (bid <= 2) {
        int b = bid - 1;
        if (tid < 128) {
            float acc = 0.0f;
            for (int n = 0; n < 224; n++) {
                int lo = (n >= NH) ? ((n - (NH - 2)) >> 1) : 0;
                int hi = min(3, n >> 1);
                acc += (float)(hi - lo + 1) * feats[(b * 224 + n) * 128 + tid];
            }
            out[b * 128 + tid] = acc * (2.0f / (float)NH);
        }
    } else {
        int idx = bid - 3;
        int b = idx / NH, h = idx - b * NH;
        for (int e = tid; e < 768; e += blockDim.x) {
            int oi = e / 24, p = e % 24;
            int i = oi & 3;
            const float* tp = types + (b * 4 + i) * 224 + h;
            float t0 = tp[0], t1 = tp[2], t2 = tp[4], t3 = tp[6];
            float t2s = t0 * t0 + t1 * t1 + t2 * t2 + t3 * t3;
            const float* krp = kr + oi * 4;
            const float* kcp = kc + oi * 4;
            float rd = t0 * krp[c_P[p][0]] + t1 * krp[c_P[p][1]] + t2 * krp[c_P[p][2]] + t3 * krp[c_P[p][3]];
            float cd = t0 * kcp[c_P[p][0]] + t1 * kcp[c_P[p][1]] + t2 * kcp[c_P[p][2]] + t3 * kcp[c_P[p][3]];
            size_t lin = ((size_t)(b * 32 + oi) * 24 + p) * NHP + h;
            g_rpn[lin] = t2s - 2.0f * rd;
            g_cpn[lin] = t2s - 2.0f * cd;
        }
    }
}

// ---------------- sims: 4 subs/thread, pre-duplicated smem operands -------
// thread = (lh in 0..3, quad-group u in 0..54): subs h2 = 4u..4u+3
// h1 = 4*blockIdx.x + lh; tiles span 220 >= NH -> h1 masking REQUIRED (R9 bug).
__global__ void __launch_bounds__(TPB, 3)
sims_kernel(const float* __restrict__ graph) {
    __shared__ __align__(16) ull sw2[8 * 24 * 16];   // 24 KB dup weights [oiL][p][c]
    __shared__ __align__(16) ull srpd[4][8][24];     // 6 KB dup (c2+rp) per h1
    __shared__ unsigned smaxu[4][8];
    __shared__ float    smaxf[4][8];
    __shared__ float    ssumv[4][8];

    int t  = threadIdx.x;
    int b  = blockIdx.y;
    int zo = blockIdx.z;              // o-pair: o = zo*2 + oL
    int h1base = blockIdx.x * 4;

    {
        const float* srcw = g_Wn + zo * 8 * 384;
        for (int e = t; e < 3072; e += TPB) sw2[e] = dup2(srcw[e]);
        for (int e = t; e < 768; e += TPB) {
            int lh = e / 192, r = e % 192, oiL = r / 24, p = r % 24;
            int h1s = min(h1base + lh, NH - 1);
            float v = g_c2[zo * 8 + oiL] +
                      g_rpn[((size_t)(b * 32 + zo * 8 + oiL) * 24 + p) * NHP + h1s];
            srpd[lh][oiL][p] = dup2(v);
        }
        if (t < 32) { smaxu[t >> 3][t & 7] = 0u; ssumv[t >> 3][t & 7] = 0.0f; }
    }
    __syncthreads();

    int lh = t / QG, u = t - lh * QG;
    int h1 = h1base + lh;
    bool h1v = h1 < NH;                               // RESTORED mask
    int h1c = h1v ? h1 : NH - 1;
    int h2b = 4 * u;
    int nk = h1v ? ((h2b + 4 <= NH) ? 4 : NH - h2b) : 0;  // 4, 2 (u=54), or 0
    bool fullq = (u < QG - 1);

    #pragma unroll 1
    for (int i = 0; i < 4; i++) {
        ull xq[4][5];
        float x20 = 0.f, x21 = 0.f, x22 = 0.f, x23 = 0.f;
        const float* gp = graph + (((size_t)(b * 4 + i) * 224) + h1c) * 224 + h2b;
        #pragma unroll
        for (int a = 0; a < 4; a++) {
            const float* ad = gp + (2 * a) * 224;
            float4 v0 = *(const float4*)ad;          // g0..g3
            float4 v1 = *(const float4*)(ad + 4);    // g4..g7
            float2 v2 = fullq ? *(const float2*)(ad + 8) : make_float2(0.f, 0.f);
            xq[a][0] = pk2(v0.x, v0.y);
            xq[a][1] = pk2(v0.z, v0.w);
            xq[a][2] = pk2(v1.x, v1.y);
            xq[a][3] = pk2(v1.z, v1.w);
            xq[a][4] = pk2(v2.x, v2.y);
            x20 = fmaf(v0.x, v0.x, fmaf(v0.z, v0.z, fmaf(v1.x, v1.x, fmaf(v1.z, v1.z, x20))));
            x21 = fmaf(v0.y, v0.y, fmaf(v0.w, v0.w, fmaf(v1.y, v1.y, fmaf(v1.w, v1.w, x21))));
            x22 = fmaf(v0.z, v0.z, fmaf(v1.x, v1.x, fmaf(v1.z, v1.z, fmaf(v2.x, v2.x, x22))));
            x23 = fmaf(v0.w, v0.w, fmaf(v1.y, v1.y, fmaf(v1.w, v1.w, fmaf(v2.y, v2.y, x23))));
        }
        ull b01 = pk2(x20, x21);
        ull b23 = pk2(x22, x23);

        #pragma unroll 1
        for (int oL = 0; oL < 2; oL++) {
            int oiL = oL * 4 + i;
            const ulonglong2* wb = (const ulonglong2*)(sw2 + oiL * 384);
            const ull* rpd = &srpd[lh][oiL][0];
            const float* cpg = g_cpn + ((size_t)(b * 32 + zo * 8 + oiL) * 24) * NHP + h2b;
            float m0 = FLT_MAX, m1 = FLT_MAX, m2 = FLT_MAX, m3 = FLT_MAX;
            #pragma unroll 4
            for (int p = 0; p < 24; p++) {
                ulonglong2 cpq = *(const ulonglong2*)(cpg + p * NHP);
                ull crp = rpd[p];                     // LDS.64, pre-dup (c2+rp)
                ull a01 = add2(add2(b01, crp), cpq.x);
                ull a23 = add2(add2(b23, crp), cpq.y);
                const ulonglong2* wp = wb + p * 8;
                #pragma unroll
                for (int j = 0; j < 8; j++) {         // c pair (2j, 2j+1)
                    ulonglong2 w = wp[j];             // LDS.128 broadcast
                    int a = j >> 1, bb = (2 * j) & 3;
                    FMA2(a01, xq[a][bb],     w.x);
                    FMA2(a23, xq[a][bb + 1], w.x);
                    FMA2(a01, xq[a][bb + 1], w.y);
                    FMA2(a23, xq[a][bb + 2], w.y);
                }
                float d0, d1, d2, d3;
                UNPK(a01, d0, d1); UNPK(a23, d2, d3);
                m0 = fminf(m0, d0); m1 = fminf(m1, d1);
                m2 = fminf(m2, d2); m3 = fminf(m3, d3);
            }
            if (nk) {
                int row = b * 32 + zo * 8 + oiL;
                float* sp = g_sims + (size_t)row * NSUB + h1 * NH + h2b;
                *(float2*)sp = make_float2(m0, m1);
                float tm = fmaxf(m0, m1);
                if (nk == 4) {
                    *(float2*)(sp + 2) = make_float2(m2, m3);
                    tm = fmaxf(tm, fmaxf(m2, m3));
                }
                unsigned uu  = __float_as_uint(tm);
                unsigned key = (uu & 0x80000000u) ? ~uu : (uu | 0x80000000u);
                atomicMax(&smaxu[lh][oiL], key);
            }
        }
    }

    __syncthreads();
    if (t < 32) {
        unsigned uu = smaxu[t >> 3][t & 7];
        smaxf[t >> 3][t & 7] = (uu & 0x80000000u) ? __uint_as_float(uu & 0x7fffffffu)
                                                  : __uint_as_float(~uu);
    }
    __syncthreads();

    // phase 2: in-place exp (thread re-reads only its own writes)
    if (nk) {
        #pragma unroll 1
        for (int oiL = 0; oiL < 8; oiL++) {
            int row = b * 32 + zo * 8 + oiL;
            float mx = smaxf[lh][oiL];
            float* sp = g_sims + (size_t)row * NSUB + h1 * NH + h2b;
            float2 v01 = *(float2*)sp;
            float e0 = __expf(v01.x - mx), e1 = __expf(v01.y - mx);
            *(float2*)sp = make_float2(e0, e1);
            float ssv = e0 + e1;
            if (nk == 4) {
                float2 v23 = *(float2*)(sp + 2);
                float e2 = __expf(v23.x - mx), e3 = __expf(v23.y - mx);
                *(float2*)(sp + 2) = make_float2(e2, e3);
                ssv += e2 + e3;
            }
            atomicAdd(&ssumv[lh][oiL], ssv);
        }
    }
    __syncthreads();
    if (t < 32) {
        int lh2 = t >> 3, oiL = t & 7, h1w = h1base + lh2;
        if (h1w < NH) {                               // RESTORED guard
            int row = b * 32 + zo * 8 + oiL;
            g_pmax[row][h1w] = smaxf[lh2][oiL];
            g_psum[row][h1w] = ssumv[lh2][oiL];
        }
    }
}

// ---------------- combine: global max/sum + factor table -------------------
__global__ void combine_kernel() {
    __shared__ float red[256];
    int row = blockIdx.x, tid = threadIdx.x;
    float pm = (tid < NH) ? g_pmax[row][tid] : -FLT_MAX;
    red[tid] = pm; __syncthreads();
    #pragma unroll
    for (int st = 128; st; st >>= 1) {
        if (tid < st) red[tid] = fmaxf(red[tid], red[tid + st]);
        __syncthreads();
    }
    float gmx = red[0];
    __syncthreads();
    float ex = (tid < NH) ? __expf(pm - gmx) : 0.0f;
    red[tid] = (tid < NH) ? g_psum[row][tid] * ex : 0.0f;
    __syncthreads();
    #pragma unroll
    for (int st = 128; st; st >>= 1) {
        if (tid < st) red[tid] += red[tid + st];
        __syncthreads();
    }
    float S = red[0];
    if (tid < NH) g_fac[row][tid] = ex / S;
}

// ---------------- writeout: grid-stride float4 streaming -------------------
__global__ void writeout_kernel(float* __restrict__ out) {
    int row = blockIdx.y;
    const float* fr = g_fac[row];
    const float* sp = g_sims + (size_t)row * NSUB;
    float* op = out + 256 + (size_t)row * NSUB;
    int idx = (blockIdx.x * 1024 + threadIdx.x) * 4;
    if (idx + 4 <= NSUB) {
        float4 e = *(const float4*)(sp + idx);
        int h1a = idx / NH, h1b = (idx + 1) / NH, h1c = (idx + 2) / NH, h1d = (idx + 3) / NH;
        float4 r;
        r.x = (1.0f - e.x * fr[h1a]) * (1.0f / (float)NSUB);
        r.y = (1.0f - e.y * fr[h1b]) * (1.0f / (float)NSUB);
        r.z = (1.0f - e.z * fr[h1c]) * (1.0f / (float)NSUB);
        r.w = (1.0f - e.w * fr[h1d]) * (1.0f / (float)NSUB);
        *(float4*)(op + idx) = r;
    } else {
        for (int j = idx; j < NSUB; j++)
            op[j] = (1.0f - sp[j] * fr[j / NH]) * (1.0f / (float)NSUB);
    }
}

// ---------------- launch ---------------------------------------------------
extern "C" void kernel_launch(void* const* d_in, const int* in_sizes, int n_in,
                              void* d_out, int out_size) {
    const float* graph    = (const float*)d_in[0];
    const float* types    = (const float*)d_in[1];
    const float* features = (const float*)d_in[2];
    const float* ks       = (const float*)d_in[3];
    const float* kr       = (const float*)d_in[4];
    const float* kc       = (const float*)d_in[5];
    float* out = (float*)d_out;

    prep_all_kernel<<<3 + 2 * NH, 256>>>(types, features, ks, kr, kc, out);
    sims_kernel<<<dim3(QG, 2, 4), TPB>>>(graph);
    combine_kernel<<<NROWS, 256>>>();
    writeout_kernel<<<dim3((NSUB + 4095) / 4096, NROWS), 1024>>>(out);
}